// round 4
// baseline (speedup 1.0000x reference)
#include <cuda_runtime.h>
#include <cuda_bf16.h>
#include <math.h>

// Problem constants (fixed by the dataset)
#define B_   16384
#define E_   128
#define S_   512
#define VOC_ 1000000

// GEMM tiling
#define BM 128
#define BN 128
#define BK 16
#define TM 8
#define TN 8
#define GEMM_THREADS 256
#define GEMM_ROW_TILES (B_ / BM)      // 128
#define GEMM_COL_TILES (S_ / BN)      // 4
#define GEMM_BLOCKS (GEMM_ROW_TILES * GEMM_COL_TILES)  // 512

#define TRUE_BLOCKS (B_ / 8)          // 2048 (8 rows per block, warp per row)

// ---- device scratch (no allocations allowed) ----
__device__ float g_Bw[S_ * E_];          // gathered sampled weight rows [s][k]
__device__ float g_corr[S_];             // biases[sampled] - log(expected_count)
__device__ float g_part_samp[GEMM_BLOCKS];
__device__ float g_part_true[TRUE_BLOCKS];
__device__ int   g_idx64;                // 1 if index buffers are int64, 0 if int32

// -------------------------------------------------------------------------
// Index dtype detection + safe load. JAX without x64 silently makes these
// int32; reference source says int64. Detect at runtime, deterministically.
// -------------------------------------------------------------------------
__global__ void k_detect(const void* __restrict__ sampled) {
    const long long* s64 = (const long long*)sampled;
    int ok64 = 1;
    for (int i = 0; i < S_; i++) {
        long long v = s64[i];
        if (v < 0 || v >= VOC_) { ok64 = 0; break; }
    }
    g_idx64 = ok64;
}

__device__ __forceinline__ int load_id(const void* p, int i) {
    long long v;
    if (g_idx64) v = ((const long long*)p)[i];
    else         v = (long long)((const int*)p)[i];
    // clamp: never allow an OOB gather even if something is off
    if (v < 0) v = 0;
    if (v >= VOC_) v = VOC_ - 1;
    return (int)v;
}

// -------------------------------------------------------------------------
// Reference-faithful  biases[id] - log(expected_count(id)).
// The f32 log(c+2)-log(c+1) difference is catastrophically cancelling, so
// emulate the reference's f32 pipeline with correctly-rounded f32 logs
// (double log rounded to f32), then the remaining ops in f32 libdevice.
// -------------------------------------------------------------------------
__device__ __forceinline__ float neg_log_expected(int id) {
    double cd = (double)id;
    float l2 = (float)log(cd + 2.0);
    float l1 = (float)log(cd + 1.0);
    float denom = (float)log((double)VOC_ + 1.0);
    float p = (l2 - l1) / denom;
    float lp = log1pf(-p);
    float e  = -expm1f(512.0f * lp);
    return -logf(e);
}

// -------------------------------------------------------------------------
// Fast softplus: max(x,0) + log1p(exp(-|x|)), FMA/ALU only on the hot path.
// -------------------------------------------------------------------------
__device__ __forceinline__ float softplus_fast(float x) {
    float u  = fabsf(x);
    float mx = fmaxf(x, 0.0f);
    float y  = fmaxf(u * -1.4426950408889634f, -25.0f);   // -|x|*log2(e)
    int   n  = __float2int_rn(y);
    float f  = y - (float)n;
    // 2^f on [-0.5, 0.5], deg-5 poly (rel err ~2e-6)
    float pe = 1.3333558146e-3f;
    pe = fmaf(pe, f, 9.6181291076e-3f);
    pe = fmaf(pe, f, 5.5504108665e-2f);
    pe = fmaf(pe, f, 2.4022650696e-1f);
    pe = fmaf(pe, f, 6.9314718056e-1f);
    pe = fmaf(pe, f, 1.0f);
    float t = pe * __int_as_float((n + 127) << 23);       // t = exp(-|x|) in (0,1]
    float l;
    if (t > 0.125f) {
        l = log1pf(t);                                    // rare, accurate path
    } else {
        // t - t^2/2 + t^3/3 - t^4/4   (abs err <= t^5/5 ~ 6e-6)
        l = t * fmaf(t, fmaf(t, fmaf(t, -0.25f, 0.33333333f), -0.5f), 1.0f);
    }
    return mx + l;
}

// -------------------------------------------------------------------------
// K1: gather sampled weight rows into contiguous buffer + per-sample corr
// grid = (S_), block = (E_)
// -------------------------------------------------------------------------
__global__ void k_gather(const float* __restrict__ W,
                         const float* __restrict__ bias,
                         const void* __restrict__ sampled) {
    int s = blockIdx.x;
    int id = load_id(sampled, s);
    const float* src = W + (size_t)id * E_;
    g_Bw[s * E_ + threadIdx.x] = src[threadIdx.x];
    if (threadIdx.x == 0) {
        g_corr[s] = bias[id] + neg_log_expected(id);
    }
}

// -------------------------------------------------------------------------
// K2: fused SGEMM (P @ Ws^T) + softplus + block-level sum.
// Block computes a BMxBN logit tile; never materializes logits.
// grid = (GEMM_ROW_TILES, GEMM_COL_TILES), block = 256
// -------------------------------------------------------------------------
__global__ __launch_bounds__(GEMM_THREADS, 2)
void k_gemm_softplus(const float* __restrict__ P) {
    __shared__ float As[BK][BM + 4];
    __shared__ float Bs[BK][BN + 4];
    __shared__ float red[GEMM_THREADS];

    const int tid = threadIdx.x;
    const int rowTile = blockIdx.x;     // 0..127
    const int colTile = blockIdx.y;     // 0..3

    const float* Abase = P    + (size_t)rowTile * BM * E_;
    const float* Bbase = g_Bw + (size_t)colTile * BN * E_;

    const int lr = tid >> 2;            // 0..63
    const int lc = (tid & 3) << 2;      // 0,4,8,12
    const int ty = tid >> 4;            // 0..15 -> m block
    const int tx = tid & 15;            // 0..15 -> n block

    float acc[TM][TN];
#pragma unroll
    for (int i = 0; i < TM; i++)
#pragma unroll
        for (int j = 0; j < TN; j++) acc[i][j] = 0.0f;

#pragma unroll
    for (int kk = 0; kk < E_; kk += BK) {
#pragma unroll
        for (int pass = 0; pass < 2; pass++) {
            int r = lr + pass * 64;
            float4 va = *(const float4*)(Abase + (size_t)r * E_ + kk + lc);
            As[lc + 0][r] = va.x; As[lc + 1][r] = va.y;
            As[lc + 2][r] = va.z; As[lc + 3][r] = va.w;
            float4 vb = *(const float4*)(Bbase + (size_t)r * E_ + kk + lc);
            Bs[lc + 0][r] = vb.x; Bs[lc + 1][r] = vb.y;
            Bs[lc + 2][r] = vb.z; Bs[lc + 3][r] = vb.w;
        }
        __syncthreads();
#pragma unroll
        for (int k = 0; k < BK; k++) {
            float a[TM], b[TN];
            *(float4*)&a[0] = *(const float4*)&As[k][ty * TM];
            *(float4*)&a[4] = *(const float4*)&As[k][ty * TM + 4];
            *(float4*)&b[0] = *(const float4*)&Bs[k][tx * TN];
            *(float4*)&b[4] = *(const float4*)&Bs[k][tx * TN + 4];
#pragma unroll
            for (int i = 0; i < TM; i++)
#pragma unroll
                for (int j = 0; j < TN; j++)
                    acc[i][j] = fmaf(a[i], b[j], acc[i][j]);
        }
        __syncthreads();
    }

    // Epilogue: x = logit + corr[col]; sum softplus(x)
    float corrv[TN];
#pragma unroll
    for (int j = 0; j < TN; j++)
        corrv[j] = g_corr[colTile * BN + tx * TN + j];

    float lsum = 0.0f;
#pragma unroll
    for (int i = 0; i < TM; i++)
#pragma unroll
        for (int j = 0; j < TN; j++)
            lsum += softplus_fast(acc[i][j] + corrv[j]);

    red[tid] = lsum;
    __syncthreads();
#pragma unroll
    for (int s = GEMM_THREADS / 2; s > 0; s >>= 1) {
        if (tid < s) red[tid] += red[tid + s];
        __syncthreads();
    }
    if (tid == 0)
        g_part_samp[blockIdx.y * gridDim.x + blockIdx.x] = red[0];
}

// -------------------------------------------------------------------------
// K3: true-class loss. Warp per row: gather weight row, dot, sce(x, 1.0).
// grid = TRUE_BLOCKS, block = 256 (8 warps = 8 rows)
// -------------------------------------------------------------------------
__global__ __launch_bounds__(256)
void k_true(const float* __restrict__ P, const float* __restrict__ W,
            const float* __restrict__ bias, const void* __restrict__ labels) {
    __shared__ float rsum[8];
    int warp = threadIdx.x >> 5;
    int lane = threadIdx.x & 31;
    int row  = blockIdx.x * 8 + warp;

    int id = load_id(labels, row);
    float4 p4 = *(const float4*)(P + (size_t)row * E_ + lane * 4);
    float4 w4 = *(const float4*)(W + (size_t)id  * E_ + lane * 4);
    float d = p4.x * w4.x + p4.y * w4.y + p4.z * w4.z + p4.w * w4.w;
#pragma unroll
    for (int off = 16; off > 0; off >>= 1)
        d += __shfl_xor_sync(0xFFFFFFFFu, d, off);

    if (lane == 0) {
        float x = d + bias[id] + neg_log_expected(id);
        // sce(x, z=1): max(x,0) - x + log1p(exp(-|x|))
        float loss = fmaxf(x, 0.0f) - x + log1pf(expf(-fabsf(x)));
        rsum[warp] = loss;
    }
    __syncthreads();
    if (threadIdx.x == 0) {
        float t = 0.0f;
#pragma unroll
        for (int i = 0; i < 8; i++) t += rsum[i];
        g_part_true[blockIdx.x] = t;
    }
}

// -------------------------------------------------------------------------
// K4: deterministic final reduction (double accumulation), write mean.
// -------------------------------------------------------------------------
__global__ void k_reduce(float* __restrict__ out) {
    __shared__ double red[256];
    int tid = threadIdx.x;
    double s = 0.0;
    for (int i = tid; i < GEMM_BLOCKS; i += 256) s += (double)g_part_samp[i];
    for (int i = tid; i < TRUE_BLOCKS; i += 256) s += (double)g_part_true[i];
    red[tid] = s;
    __syncthreads();
#pragma unroll
    for (int k = 128; k > 0; k >>= 1) {
        if (tid < k) red[tid] += red[tid + k];
        __syncthreads();
    }
    if (tid == 0) out[0] = (float)(red[0] / (double)B_);
}

// -------------------------------------------------------------------------
extern "C" void kernel_launch(void* const* d_in, const int* in_sizes, int n_in,
                              void* d_out, int out_size) {
    const float* pred    = (const float*)d_in[0];   // [B, E]
    const float* weights = (const float*)d_in[1];   // [V, E]
    const float* biases  = (const float*)d_in[2];   // [V]
    const void*  labels  = d_in[3];                 // [B, 1] int32 or int64
    const void*  sampled = d_in[4];                 // [S]    int32 or int64
    float* out = (float*)d_out;

    k_detect<<<1, 1>>>(sampled);
    k_gather<<<S_, E_>>>(weights, biases, sampled);
    k_gemm_softplus<<<dim3(GEMM_ROW_TILES, GEMM_COL_TILES), GEMM_THREADS>>>(pred);
    k_true<<<TRUE_BLOCKS, 256>>>(pred, weights, biases, labels);
    k_reduce<<<1, 256>>>(out);
}

// round 5
// speedup vs baseline: 3.2081x; 3.2081x over previous
#include <cuda_runtime.h>
#include <cuda_bf16.h>
#include <math.h>
#include <stdint.h>

// Problem constants (fixed by the dataset)
#define B_   16384
#define E_   128
#define S_   512
#define VOC_ 1000000

#define GEMM_ROW_TILES (B_ / 128)     // 128
#define GEMM_COL_TILES (S_ / 128)     // 4
#define GEMM_BLOCKS (GEMM_ROW_TILES * GEMM_COL_TILES)  // 512
#define TRUE_BLOCKS (B_ / 8)          // 2048

// ---- device scratch (no allocations allowed) ----
__device__ float g_Bw[S_ * E_];          // gathered sampled weight rows [s][k]
__device__ float g_corr[S_];             // biases[sampled] - log(expected_count)
__device__ float g_tcorr[B_];            // biases[label]   - log(expected_count)
__device__ float g_part_samp[GEMM_BLOCKS];
__device__ float g_part_true[TRUE_BLOCKS];
__device__ int   g_idx64;                // 1 if index buffers are int64, 0 if int32

// -------------------------------------------------------------------------
// Index dtype detection (parallel). JAX without x64 silently makes these
// int32; reference source says int64. If int32 data is read as int64 the
// high word holds the next id (~uniform on [0,1e6)), so OOB => int32.
// -------------------------------------------------------------------------
__global__ void k_detect(const void* __restrict__ sampled) {
    __shared__ int bad;
    if (threadIdx.x == 0) bad = 0;
    __syncthreads();
    const long long* s64 = (const long long*)sampled;
    for (int i = threadIdx.x; i < S_; i += 256) {
        long long v = s64[i];
        if (v < 0 || v >= VOC_) bad = 1;
    }
    __syncthreads();
    if (threadIdx.x == 0) g_idx64 = bad ? 0 : 1;
}

__device__ __forceinline__ int load_id(const void* p, int i) {
    long long v;
    if (g_idx64) v = ((const long long*)p)[i];
    else         v = (long long)((const int*)p)[i];
    if (v < 0) v = 0;
    if (v >= VOC_) v = VOC_ - 1;
    return (int)v;
}

// -------------------------------------------------------------------------
// Reference-faithful  -log(expected_count(id)).  The f32 log(c+2)-log(c+1)
// difference is catastrophically cancelling; emulate the reference's f32
// pipeline with correctly-rounded f32 logs (double log rounded to f32).
// -------------------------------------------------------------------------
__device__ __forceinline__ float neg_log_expected(int id) {
    double cd = (double)id;
    float l2 = (float)log(cd + 2.0);
    float l1 = (float)log(cd + 1.0);
    float denom = (float)log((double)VOC_ + 1.0);
    float p = (l2 - l1) / denom;
    float lp = log1pf(-p);
    float e  = -expm1f(512.0f * lp);
    return -logf(e);
}

// -------------------------------------------------------------------------
// Fast softplus: max(x,0) + log1p(exp(-|x|)), FMA/ALU only on the hot path.
// -------------------------------------------------------------------------
__device__ __forceinline__ float softplus_fast(float x) {
    float u  = fabsf(x);
    float mx = fmaxf(x, 0.0f);
    float y  = fmaxf(u * -1.4426950408889634f, -25.0f);   // -|x|*log2(e)
    int   n  = __float2int_rn(y);
    float f  = y - (float)n;
    float pe = 1.3333558146e-3f;
    pe = fmaf(pe, f, 9.6181291076e-3f);
    pe = fmaf(pe, f, 5.5504108665e-2f);
    pe = fmaf(pe, f, 2.4022650696e-1f);
    pe = fmaf(pe, f, 6.9314718056e-1f);
    pe = fmaf(pe, f, 1.0f);
    float t = pe * __int_as_float((n + 127) << 23);       // exp(-|x|) in (0,1]
    float l;
    if (t > 0.125f) {
        l = log1pf(t);
    } else {
        l = t * fmaf(t, fmaf(t, fmaf(t, -0.25f, 0.33333333f), -0.5f), 1.0f);
    }
    return mx + l;
}

__device__ __forceinline__ uint32_t f2tf32(float x) {
    uint32_t r;
    asm("cvt.rna.tf32.f32 %0, %1;" : "=r"(r) : "f"(x));
    return r;
}

// -------------------------------------------------------------------------
// K1: gather sampled weight rows + per-sample corr. grid=(S_), block=(E_)
// -------------------------------------------------------------------------
__global__ void k_gather(const float* __restrict__ W,
                         const float* __restrict__ bias,
                         const void* __restrict__ sampled) {
    int s = blockIdx.x;
    int id = load_id(sampled, s);
    g_Bw[s * E_ + threadIdx.x] = W[(size_t)id * E_ + threadIdx.x];
    if (threadIdx.x == 0)
        g_corr[s] = bias[id] + neg_log_expected(id);
}

// -------------------------------------------------------------------------
// K2: per-label correction, fully parallel (hoists fp64 logs off the
// k_true warp critical path). grid=64, block=256
// -------------------------------------------------------------------------
__global__ void k_corr(const float* __restrict__ bias,
                       const void* __restrict__ labels) {
    int i = blockIdx.x * 256 + threadIdx.x;
    int id = load_id(labels, i);
    g_tcorr[i] = bias[id] + neg_log_expected(id);
}

// -------------------------------------------------------------------------
// K3: tensor-core tf32 GEMM (P @ Ws^T) + softplus + block sum.
// Block tile 128x128, 8 warps (4x2), warp tile 32x64, mma.m16n8k8.
// Smem row-major with stride 36 words: fragment LDS are conflict-free.
// -------------------------------------------------------------------------
#define AS_STRIDE 36
__global__ __launch_bounds__(256, 2)
void k_gemm_tc(const float* __restrict__ P) {
    __shared__ uint32_t As[128 * AS_STRIDE];   // [row][k] tf32 bits
    __shared__ uint32_t Bs[128 * AS_STRIDE];   // [col][k] tf32 bits
    __shared__ float red[256];

    const int tid  = threadIdx.x;
    const int lane = tid & 31;
    const int warp = tid >> 5;
    const int warpRow = warp & 3;        // 0..3 -> M offset *32
    const int warpCol = warp >> 2;       // 0..1 -> N offset *64
    const int g = lane >> 2;             // groupID 0..7
    const int q = lane & 3;              // tid in group 0..3

    const float* Abase = P    + (size_t)blockIdx.x * 128 * E_;
    const float* Bbase = g_Bw + (size_t)blockIdx.y * 128 * E_;

    float acc[2][8][4];
#pragma unroll
    for (int mi = 0; mi < 2; mi++)
#pragma unroll
        for (int ni = 0; ni < 8; ni++)
#pragma unroll
            for (int r = 0; r < 4; r++) acc[mi][ni][r] = 0.0f;

#pragma unroll
    for (int kk = 0; kk < E_; kk += 32) {
        // stage A and B tiles: 128 rows x 32 k each; 1024 float4 per tile
#pragma unroll
        for (int i = 0; i < 4; i++) {
            int idx = tid + 256 * i;
            int row = idx >> 3;
            int c   = (idx & 7) * 4;
            float4 va = *(const float4*)(Abase + (size_t)row * E_ + kk + c);
            uint32_t* d = &As[row * AS_STRIDE + c];
            d[0] = f2tf32(va.x); d[1] = f2tf32(va.y);
            d[2] = f2tf32(va.z); d[3] = f2tf32(va.w);
            float4 vb = *(const float4*)(Bbase + (size_t)row * E_ + kk + c);
            uint32_t* e = &Bs[row * AS_STRIDE + c];
            e[0] = f2tf32(vb.x); e[1] = f2tf32(vb.y);
            e[2] = f2tf32(vb.z); e[3] = f2tf32(vb.w);
        }
        __syncthreads();

#pragma unroll
        for (int ks = 0; ks < 4; ks++) {
            const int kb = ks * 8;
            uint32_t a[2][4];
#pragma unroll
            for (int mi = 0; mi < 2; mi++) {
                int r0 = warpRow * 32 + mi * 16 + g;
                a[mi][0] = As[r0 * AS_STRIDE + kb + q];
                a[mi][1] = As[(r0 + 8) * AS_STRIDE + kb + q];
                a[mi][2] = As[r0 * AS_STRIDE + kb + q + 4];
                a[mi][3] = As[(r0 + 8) * AS_STRIDE + kb + q + 4];
            }
#pragma unroll
            for (int ni = 0; ni < 8; ni++) {
                int c0 = warpCol * 64 + ni * 8 + g;
                uint32_t b0 = Bs[c0 * AS_STRIDE + kb + q];
                uint32_t b1 = Bs[c0 * AS_STRIDE + kb + q + 4];
#pragma unroll
                for (int mi = 0; mi < 2; mi++) {
                    asm volatile(
                        "mma.sync.aligned.m16n8k8.row.col.f32.tf32.tf32.f32 "
                        "{%0,%1,%2,%3}, {%4,%5,%6,%7}, {%8,%9}, {%0,%1,%2,%3};"
                        : "+f"(acc[mi][ni][0]), "+f"(acc[mi][ni][1]),
                          "+f"(acc[mi][ni][2]), "+f"(acc[mi][ni][3])
                        : "r"(a[mi][0]), "r"(a[mi][1]), "r"(a[mi][2]), "r"(a[mi][3]),
                          "r"(b0), "r"(b1));
                }
            }
        }
        __syncthreads();
    }

    // Epilogue: col of acc[mi][ni][r] = warpCol*64 + ni*8 + q*2 + (r&1)
    const float* corrBase = g_corr + blockIdx.y * 128 + warpCol * 64;
    float lsum = 0.0f;
#pragma unroll
    for (int ni = 0; ni < 8; ni++) {
        float c0 = corrBase[ni * 8 + q * 2];
        float c1 = corrBase[ni * 8 + q * 2 + 1];
#pragma unroll
        for (int mi = 0; mi < 2; mi++) {
            lsum += softplus_fast(acc[mi][ni][0] + c0);
            lsum += softplus_fast(acc[mi][ni][1] + c1);
            lsum += softplus_fast(acc[mi][ni][2] + c0);
            lsum += softplus_fast(acc[mi][ni][3] + c1);
        }
    }

    red[tid] = lsum;
    __syncthreads();
#pragma unroll
    for (int s = 128; s > 0; s >>= 1) {
        if (tid < s) red[tid] += red[tid + s];
        __syncthreads();
    }
    if (tid == 0)
        g_part_samp[blockIdx.y * gridDim.x + blockIdx.x] = red[0];
}

// -------------------------------------------------------------------------
// K4: true-class loss. Warp per row; correction precomputed.
// grid = TRUE_BLOCKS, block = 256
// -------------------------------------------------------------------------
__global__ __launch_bounds__(256)
void k_true(const float* __restrict__ P, const float* __restrict__ W,
            const void* __restrict__ labels) {
    __shared__ float rsum[8];
    int warp = threadIdx.x >> 5;
    int lane = threadIdx.x & 31;
    int row  = blockIdx.x * 8 + warp;

    int id = load_id(labels, row);
    float4 p4 = *(const float4*)(P + (size_t)row * E_ + lane * 4);
    float4 w4 = *(const float4*)(W + (size_t)id  * E_ + lane * 4);
    float d = p4.x * w4.x + p4.y * w4.y + p4.z * w4.z + p4.w * w4.w;
#pragma unroll
    for (int off = 16; off > 0; off >>= 1)
        d += __shfl_xor_sync(0xFFFFFFFFu, d, off);

    if (lane == 0) {
        float x = d + g_tcorr[row];
        // sce(x, z=1): max(x,0) - x + log1p(exp(-|x|))
        float loss = fmaxf(x, 0.0f) - x + softplus_fast(x) - fmaxf(x, 0.0f);
        // (softplus_fast(x) = max(x,0)+log1p(exp(-|x|)); combine carefully)
        loss = softplus_fast(x) - x;
        rsum[warp] = loss;
    }
    __syncthreads();
    if (threadIdx.x == 0) {
        float t = 0.0f;
#pragma unroll
        for (int i = 0; i < 8; i++) t += rsum[i];
        g_part_true[blockIdx.x] = t;
    }
}

// -------------------------------------------------------------------------
// K5: deterministic final reduction (double accumulation), write mean.
// -------------------------------------------------------------------------
__global__ void k_reduce(float* __restrict__ out) {
    __shared__ double red[256];
    int tid = threadIdx.x;
    double s = 0.0;
    for (int i = tid; i < GEMM_BLOCKS; i += 256) s += (double)g_part_samp[i];
    for (int i = tid; i < TRUE_BLOCKS; i += 256) s += (double)g_part_true[i];
    red[tid] = s;
    __syncthreads();
#pragma unroll
    for (int k = 128; k > 0; k >>= 1) {
        if (tid < k) red[tid] += red[tid + k];
        __syncthreads();
    }
    if (tid == 0) out[0] = (float)(red[0] / (double)B_);
}

// -------------------------------------------------------------------------
extern "C" void kernel_launch(void* const* d_in, const int* in_sizes, int n_in,
                              void* d_out, int out_size) {
    const float* pred    = (const float*)d_in[0];   // [B, E]
    const float* weights = (const float*)d_in[1];   // [V, E]
    const float* biases  = (const float*)d_in[2];   // [V]
    const void*  labels  = d_in[3];                 // [B, 1] int32 or int64
    const void*  sampled = d_in[4];                 // [S]    int32 or int64
    float* out = (float*)d_out;

    k_detect<<<1, 256>>>(sampled);
    k_gather<<<S_, E_>>>(weights, biases, sampled);
    k_corr<<<B_ / 256, 256>>>(biases, labels);
    k_gemm_tc<<<dim3(GEMM_ROW_TILES, GEMM_COL_TILES), 256>>>(pred);
    k_true<<<TRUE_BLOCKS, 256>>>(pred, weights, labels);
    k_reduce<<<1, 256>>>(out);
}

// round 8
// speedup vs baseline: 4.5414x; 1.4156x over previous
#include <cuda_runtime.h>
#include <cuda_bf16.h>
#include <math.h>
#include <stdint.h>

// Problem constants (fixed by the dataset)
#define B_   16384
#define E_   128
#define S_   512
#define VOC_ 1000000

#define GEMM_BLK 512                  // 128 row-tiles x 4 col-tiles
#define TRUE_BLK 512                  // 32 rows each
#define NBLK (GEMM_BLK + TRUE_BLK)

#define TILE_BYTES 32768              // 128 rows x 128 bf16 (256B/row)
#define DYN_SMEM (2 * TILE_BYTES)

// ---- device scratch (no allocations allowed) ----
__device__ uint32_t g_Bsw[4 * TILE_BYTES / 4]; // pre-swizzled bf16 B tiles
__device__ float g_corr[S_];
__device__ float g_tcorr[B_];
__device__ float g_part_samp[GEMM_BLK];
__device__ float g_part_true[TRUE_BLK];
__device__ int   g_idx64;

__device__ __forceinline__ uint32_t smem_u32(const void* p) {
    uint32_t a;
    asm("{ .reg .u64 t; cvta.to.shared.u64 t, %1; cvt.u32.u64 %0, t; }"
        : "=r"(a) : "l"(p));
    return a;
}

// Swizzled tile layout: [row r][16B chunk c], phys chunk = c ^ (r&7).
// Conflict-free for both staging stores and ldmatrix reads.
__device__ __forceinline__ uint32_t tile_off(int r, int c) {
    return (uint32_t)(r * 256 + ((c ^ (r & 7)) << 4));
}

// -------------------------------------------------------------------------
// Index dtype detection + safe load (JAX may hand int32 despite int64 source)
// -------------------------------------------------------------------------
__global__ void k_detect(const void* __restrict__ sampled) {
    __shared__ int bad;
    if (threadIdx.x == 0) bad = 0;
    __syncthreads();
    const long long* s64 = (const long long*)sampled;
    for (int i = threadIdx.x; i < S_; i += 256) {
        long long v = s64[i];
        if (v < 0 || v >= VOC_) bad = 1;
    }
    __syncthreads();
    if (threadIdx.x == 0) g_idx64 = bad ? 0 : 1;
}
__device__ __forceinline__ int load_id(const void* p, int i) {
    long long v;
    if (g_idx64) v = ((const long long*)p)[i];
    else         v = (long long)((const int*)p)[i];
    if (v < 0) v = 0;
    if (v >= VOC_) v = VOC_ - 1;
    return (int)v;
}

// -------------------------------------------------------------------------
// Reference-faithful  -log(expected_count(id))  (cancellation-safe)
// -------------------------------------------------------------------------
__device__ __forceinline__ float neg_log_expected(int id) {
    double cd = (double)id;
    float l2 = (float)log(cd + 2.0);
    float l1 = (float)log(cd + 1.0);
    float denom = (float)log((double)VOC_ + 1.0);
    float p = (l2 - l1) / denom;
    float lp = log1pf(-p);
    float e  = -expm1f(512.0f * lp);
    return -logf(e);
}

// -------------------------------------------------------------------------
// Fast softplus: max(x,0) + log1p(exp(-|x|)); FMA/ALU hot path.
// -------------------------------------------------------------------------
__device__ __forceinline__ float softplus_fast(float x) {
    float u  = fabsf(x);
    float mx = fmaxf(x, 0.0f);
    float y  = fmaxf(u * -1.4426950408889634f, -25.0f);
    int   n  = __float2int_rn(y);
    float f  = y - (float)n;
    float pe = 1.3333558146e-3f;
    pe = fmaf(pe, f, 9.6181291076e-3f);
    pe = fmaf(pe, f, 5.5504108665e-2f);
    pe = fmaf(pe, f, 2.4022650696e-1f);
    pe = fmaf(pe, f, 6.9314718056e-1f);
    pe = fmaf(pe, f, 1.0f);
    float t = pe * __int_as_float((n + 127) << 23);
    float l;
    if (t > 0.125f) {
        l = log1pf(t);
    } else {
        l = t * fmaf(t, fmaf(t, fmaf(t, -0.25f, 0.33333333f), -0.5f), 1.0f);
    }
    return mx + l;
}

__device__ __forceinline__ uint32_t pack_bf(float a, float b) {
    __nv_bfloat162 h = __floats2bfloat162_rn(a, b);
    return *reinterpret_cast<uint32_t*>(&h);
}

// -------------------------------------------------------------------------
// K_prep: blocks 0..63 gather sampled weight rows -> pre-swizzled bf16 tiles
//         (+ per-sample corr); blocks 64..191 compute per-label corr.
// -------------------------------------------------------------------------
__global__ void k_prep(const float* __restrict__ W, const float* __restrict__ bias,
                       const void* __restrict__ sampled, const void* __restrict__ labels) {
    int bx = blockIdx.x, t = threadIdx.x;
    if (bx < 64) {
        int sl = t >> 4;                 // 0..7 sample within block
        int kg = t & 15;                 // 16B k-chunk
        int s  = bx * 8 + sl;
        int id = load_id(sampled, s);
        const float* src = W + (size_t)id * E_ + kg * 8;
        float4 v0 = *(const float4*)src;
        float4 v1 = *(const float4*)(src + 4);
        uint4 u;
        u.x = pack_bf(v0.x, v0.y); u.y = pack_bf(v0.z, v0.w);
        u.z = pack_bf(v1.x, v1.y); u.w = pack_bf(v1.z, v1.w);
        int colTile = s >> 7, n = s & 127;
        *(uint4*)((char*)g_Bsw + colTile * TILE_BYTES + tile_off(n, kg)) = u;
        if (kg == 0)
            g_corr[s] = bias[id] + neg_log_expected(id);
    } else {
        int i = (bx - 64) * 128 + t;
        int id = load_id(labels, i);
        g_tcorr[i] = bias[id] + neg_log_expected(id);
    }
}

#define LDMX4(r0, r1, r2, r3, addr) \
    asm volatile("ldmatrix.sync.aligned.m8n8.x4.shared.b16 {%0,%1,%2,%3}, [%4];" \
                 : "=r"(r0), "=r"(r1), "=r"(r2), "=r"(r3) : "r"(addr))

#define MMA16816(c, a, b0, b1) \
    asm volatile("mma.sync.aligned.m16n8k16.row.col.f32.bf16.bf16.f32 " \
                 "{%0,%1,%2,%3}, {%4,%5,%6,%7}, {%8,%9}, {%0,%1,%2,%3};" \
                 : "+f"((c)[0]), "+f"((c)[1]), "+f"((c)[2]), "+f"((c)[3]) \
                 : "r"((a)[0]), "r"((a)[1]), "r"((a)[2]), "r"((a)[3]), \
                   "r"(b0), "r"(b1))

// -------------------------------------------------------------------------
// K_main: blocks 0..511  -> bf16 HMMA GEMM tile + softplus + reduce
//         blocks 512..1023 -> true-class loss (32 rows each)
// block = 256 threads (8 warps, 4x2), warp tile 32x64, dyn smem = 64KB
// -------------------------------------------------------------------------
__global__ __launch_bounds__(256, 2)
void k_main(const float* __restrict__ P, const float* __restrict__ W,
            const void* __restrict__ labels) {
    __shared__ float red[256];
    extern __shared__ char dyn[];

    const int bx = blockIdx.x;
    const int tid = threadIdx.x, lane = tid & 31, wid = tid >> 5;

    if (bx < GEMM_BLK) {
        const int rowTile = bx >> 2, colTile = bx & 3;
        char* Abuf = dyn;
        char* Bbuf = dyn + TILE_BYTES;

        // Stage A (f32 -> bf16, swizzled) and B (raw 16B copy, pre-swizzled)
        const float* Abase = P + (size_t)rowTile * 128 * E_;
#pragma unroll
        for (int i = 0; i < 8; i++) {
            int gidx = tid + 256 * i;              // 0..2047
            int r = gidx >> 4, c = gidx & 15;
            const float* src = Abase + (size_t)r * E_ + c * 8;
            float4 v0 = *(const float4*)src;
            float4 v1 = *(const float4*)(src + 4);
            uint4 u;
            u.x = pack_bf(v0.x, v0.y); u.y = pack_bf(v0.z, v0.w);
            u.z = pack_bf(v1.x, v1.y); u.w = pack_bf(v1.z, v1.w);
            *(uint4*)(Abuf + tile_off(r, c)) = u;
        }
        const uint4* Bsrc = (const uint4*)((const char*)g_Bsw + colTile * TILE_BYTES);
#pragma unroll
        for (int i = 0; i < 8; i++)
            ((uint4*)Bbuf)[tid + 256 * i] = Bsrc[tid + 256 * i];
        __syncthreads();

        const int warpRow = wid & 3;          // m offset *32
        const int warpCol = wid >> 1 >> 1;    // wid>>2: n offset *64
        const int lrow = lane & 15;
        const int lhi  = lane >> 4;           // k-chunk parity for ldmatrix

        const uint32_t a_s = smem_u32(Abuf);
        const uint32_t b_s = smem_u32(Bbuf);

        // Per-lane row bases for ldmatrix addressing
        int arow[2], brow[4];
#pragma unroll
        for (int mi = 0; mi < 2; mi++) arow[mi] = warpRow * 32 + mi * 16 + lrow;
#pragma unroll
        for (int nj = 0; nj < 4; nj++) brow[nj] = warpCol * 64 + nj * 16 + lrow;

        float acc[2][8][4];
#pragma unroll
        for (int mi = 0; mi < 2; mi++)
#pragma unroll
            for (int ni = 0; ni < 8; ni++)
#pragma unroll
                for (int r = 0; r < 4; r++) acc[mi][ni][r] = 0.0f;

#pragma unroll
        for (int ks = 0; ks < 8; ks++) {
            const int chunk = ks * 2 + lhi;
            uint32_t a[2][4];
#pragma unroll
            for (int mi = 0; mi < 2; mi++) {
                uint32_t addr = a_s + (uint32_t)(arow[mi] * 256
                               + ((chunk ^ (arow[mi] & 7)) << 4));
                LDMX4(a[mi][0], a[mi][1], a[mi][2], a[mi][3], addr);
            }
            uint32_t bb[4][4];
#pragma unroll
            for (int nj = 0; nj < 4; nj++) {
                uint32_t addr = b_s + (uint32_t)(brow[nj] * 256
                               + ((chunk ^ (brow[nj] & 7)) << 4));
                LDMX4(bb[nj][0], bb[nj][1], bb[nj][2], bb[nj][3], addr);
            }
#pragma unroll
            for (int mi = 0; mi < 2; mi++)
#pragma unroll
                for (int ni = 0; ni < 8; ni++)
                    MMA16816(acc[mi][ni], a[mi],
                             bb[ni >> 1][ni & 1], bb[ni >> 1][2 + (ni & 1)]);
        }

        // Epilogue. acc[mi][ni]: rows warpRow*32+mi*16+g (+8), cols
        // warpCol*64+ni*8+q*2 (+1), g=lane>>2, q=lane&3.
        const int q = lane & 3;
        const float* corrB = g_corr + colTile * 128 + warpCol * 64;
        float lsum = 0.0f;
#pragma unroll
        for (int ni = 0; ni < 8; ni++) {
            float c0 = corrB[ni * 8 + q * 2];
            float c1 = corrB[ni * 8 + q * 2 + 1];
#pragma unroll
            for (int mi = 0; mi < 2; mi++) {
                lsum += softplus_fast(acc[mi][ni][0] + c0);
                lsum += softplus_fast(acc[mi][ni][1] + c1);
                lsum += softplus_fast(acc[mi][ni][2] + c0);
                lsum += softplus_fast(acc[mi][ni][3] + c1);
            }
        }

        red[tid] = lsum;
        __syncthreads();
#pragma unroll
        for (int s = 128; s > 0; s >>= 1) {
            if (tid < s) red[tid] += red[tid + s];
            __syncthreads();
        }
        if (tid == 0) g_part_samp[bx] = red[0];
    } else {
        // True-class loss: 32 rows per block, warp handles 4 rows
        int rb = bx - GEMM_BLK;
        float wsum = 0.0f;
#pragma unroll
        for (int i = 0; i < 4; i++) {
            int row = rb * 32 + wid * 4 + i;
            int id = load_id(labels, row);
            float4 p4 = *(const float4*)(P + (size_t)row * E_ + lane * 4);
            float4 w4 = *(const float4*)(W + (size_t)id  * E_ + lane * 4);
            float d = p4.x * w4.x + p4.y * w4.y + p4.z * w4.z + p4.w * w4.w;
#pragma unroll
            for (int off = 16; off > 0; off >>= 1)
                d += __shfl_xor_sync(0xFFFFFFFFu, d, off);
            if (lane == 0) {
                float x = d + g_tcorr[row];
                wsum += softplus_fast(x) - x;   // sce(x, z=1)
            }
        }
        red[tid] = (lane == 0) ? wsum : 0.0f;
        __syncthreads();
#pragma unroll
        for (int s = 128; s > 0; s >>= 1) {
            if (tid < s) red[tid] += red[tid + s];
            __syncthreads();
        }
        if (tid == 0) g_part_true[rb] = red[0];
    }
}

// -------------------------------------------------------------------------
// K_reduce: deterministic final reduction (double accumulation), write mean.
// -------------------------------------------------------------------------
__global__ void k_reduce(float* __restrict__ out) {
    __shared__ double red[256];
    int tid = threadIdx.x;
    double s = 0.0;
    for (int i = tid; i < GEMM_BLK; i += 256) s += (double)g_part_samp[i];
    for (int i = tid; i < TRUE_BLK; i += 256) s += (double)g_part_true[i];
    red[tid] = s;
    __syncthreads();
#pragma unroll
    for (int k = 128; k > 0; k >>= 1) {
        if (tid < k) red[tid] += red[tid + k];
        __syncthreads();
    }
    if (tid == 0) out[0] = (float)(red[0] / (double)B_);
}

// -------------------------------------------------------------------------
extern "C" void kernel_launch(void* const* d_in, const int* in_sizes, int n_in,
                              void* d_out, int out_size) {
    const float* pred    = (const float*)d_in[0];   // [B, E]
    const float* weights = (const float*)d_in[1];   // [V, E]
    const float* biases  = (const float*)d_in[2];   // [V]
    const void*  labels  = d_in[3];                 // [B, 1] int32 or int64
    const void*  sampled = d_in[4];                 // [S]
    float* out = (float*)d_out;

    static int attr_done = 0;
    if (!attr_done) {
        cudaFuncSetAttribute(k_main, cudaFuncAttributeMaxDynamicSharedMemorySize,
                             DYN_SMEM);
        attr_done = 1;
    }

    k_detect<<<1, 256>>>(sampled);
    k_prep<<<192, 128>>>(weights, biases, sampled, labels);
    k_main<<<NBLK, 256, DYN_SMEM>>>(pred, weights, labels);
    k_reduce<<<1, 256>>>(out);
}